// round 1
// baseline (speedup 1.0000x reference)
#include <cuda_runtime.h>
#include <cuda_bf16.h>
#include <mma.h>

using namespace nvcuda;

// Problem constants (fixed by the dataset)
#define B_   8
#define K_   288
#define L_   16384
#define O_   64
#define LT   128      // l-tile per CTA
#define NTHREADS 256

// Precomputed weight data (written by prep kernel each launch; deterministic)
__device__ __nv_bfloat16 g_wbf[K_ * O_];
__device__ float         g_w2[O_];

__global__ void gauss_prep_kernel(const float* __restrict__ w) {
    int t = threadIdx.x;
    for (int i = t; i < K_ * O_; i += NTHREADS)
        g_wbf[i] = __float2bfloat16(w[i]);
    if (t < O_) {
        float s = 0.f;
        #pragma unroll 4
        for (int k = 0; k < K_; ++k) {
            float v = w[k * O_ + t];
            s += v * v;
        }
        g_w2[t] = s;
    }
}

extern __shared__ char g_smem[];

// Shared layout (bytes):
//   xs   : [0, 73728)            K_*LT bf16  (x tile, [k][l])
//   ws   : [73728, 110592)       K_*O_ bf16  (w tile, [k][o])
//   x2   : [110592, 111104)      LT f32
//   x2p  : [111104, 112128)      2*LT f32
//   w2s  : [112128, 112384)      O_ f32
//   bs   : [112384, 112640)      O_ f32
//   sOut : reuses [0, 32768)     LT*O_ f32 (after MMA loop)
#define SMEM_BYTES (K_*LT*2 + K_*O_*2 + LT*4 + 2*LT*4 + O_*4 + O_*4)

__global__ __launch_bounds__(NTHREADS, 2)
void gauss_main_kernel(const float* __restrict__ x,
                       const float* __restrict__ bias,
                       const float* __restrict__ gamma_p,
                       float* __restrict__ out) {
    __nv_bfloat16* xs  = (__nv_bfloat16*)g_smem;
    __nv_bfloat16* ws  = (__nv_bfloat16*)(g_smem + K_*LT*2);
    float*         x2  = (float*)(g_smem + K_*LT*2 + K_*O_*2);
    float*         x2p = x2 + LT;
    float*         w2s = x2p + 2*LT;
    float*         bs  = w2s + O_;
    float*         sOut = (float*)g_smem;   // reuse of xs region post-MMA

    const int t  = threadIdx.x;
    const int bx = blockIdx.x;
    const int b  = bx >> 7;              // / (L_/LT) = 128
    const int l0 = (bx & 127) * LT;

    // --- stage W (bf16) + w2 + bias into smem ---
    for (int i = t; i < K_ * O_; i += NTHREADS) ws[i] = g_wbf[i];
    if (t < O_) { w2s[t] = g_w2[t]; bs[t] = bias[t]; }

    // --- stage X tile (fp32 -> bf16), accumulate x2 partials in fp32 ---
    const int lidx = t & (LT - 1);
    const int kg   = t >> 7;             // 0..1
    const float* xb = x + (b * K_) * L_ + l0;
    float acc = 0.f;
    #pragma unroll 4
    for (int k = kg; k < K_; k += 2) {
        float v = xb[k * L_ + lidx];     // coalesced: 128 consecutive l per k
        xs[k * LT + lidx] = __float2bfloat16(v);
        acc = fmaf(v, v, acc);
    }
    x2p[kg * LT + lidx] = acc;
    __syncthreads();
    if (t < LT) x2[t] = x2p[t] + x2p[LT + t];

    // --- MMA mainloop: each warp owns one 16-l tile, loops over 4 o-tiles ---
    const int warp = t >> 5;             // 0..7
    wmma::fragment<wmma::accumulator, 16, 16, 16, float> accf[4];
    #pragma unroll
    for (int i = 0; i < 4; ++i) wmma::fill_fragment(accf[i], 0.f);

    #pragma unroll 1
    for (int ks = 0; ks < K_ / 16; ++ks) {
        wmma::fragment<wmma::matrix_a, 16, 16, 16, __nv_bfloat16, wmma::col_major> af;
        // A element (row=l, col=k) lives at xs[k*LT + l]  -> col_major, ld = LT
        wmma::load_matrix_sync(af, xs + ks * 16 * LT + warp * 16, LT);
        #pragma unroll
        for (int ot = 0; ot < 4; ++ot) {
            wmma::fragment<wmma::matrix_b, 16, 16, 16, __nv_bfloat16, wmma::row_major> bf;
            wmma::load_matrix_sync(bf, ws + ks * 16 * O_ + ot * 16, O_);
            wmma::mma_sync(accf[ot], af, bf, accf[ot]);
        }
    }

    // --- epilogue: stage xw to smem, then fused exp + bias, coalesced stores ---
    __syncthreads();  // all warps done reading xs before sOut overwrites it
    #pragma unroll
    for (int ot = 0; ot < 4; ++ot)
        wmma::store_matrix_sync(sOut + (warp * 16) * O_ + ot * 16, accf[ot],
                                O_, wmma::mem_row_major);
    __syncthreads();

    const float gamma = *gamma_p;
    float* ob = out + (b * L_ + l0) * O_;
    #pragma unroll
    for (int idx = t; idx < LT * O_; idx += NTHREADS) {
        const int l = idx >> 6;
        const int o = idx & 63;
        const float d2 = x2[l] + w2s[o] - 2.f * sOut[idx];
        ob[idx] = __expf(-gamma * d2) + bs[o];
    }
}

extern "C" void kernel_launch(void* const* d_in, const int* in_sizes, int n_in,
                              void* d_out, int out_size) {
    const float* x     = (const float*)d_in[0];   // [B, K, L] fp32
    const float* w     = (const float*)d_in[1];   // [O,32,3,3] fp32 (flat K*O)
    const float* bias  = (const float*)d_in[2];   // [O] fp32
    const float* gamma = (const float*)d_in[3];   // scalar fp32
    float* out = (float*)d_out;                   // [B, L, O] fp32

    static bool attr_done = false;
    // cudaFuncSetAttribute is a host-side, non-stream call: safe under capture.
    cudaFuncSetAttribute(gauss_main_kernel,
                         cudaFuncAttributeMaxDynamicSharedMemorySize, SMEM_BYTES);

    gauss_prep_kernel<<<1, NTHREADS>>>(w);
    gauss_main_kernel<<<B_ * (L_ / LT), NTHREADS, SMEM_BYTES>>>(x, bias, gamma, out);
    (void)attr_done; (void)in_sizes; (void)n_in; (void)out_size;
}

// round 2
// speedup vs baseline: 2.5096x; 2.5096x over previous
#include <cuda_runtime.h>
#include <cuda_bf16.h>
#include <mma.h>

using namespace nvcuda;

#define B_   8
#define K_   288
#define L_   16384
#define O_   64
#define LT   128       // l-tile per CTA
#define CH   32        // k-rows per pipeline chunk
#define NCH  (K_/CH)   // 9 chunks
#define STAGES 3
#define NTHREADS 256

#define WS_LD   72     // padded B (weights) row stride, elems
#define XA_LD   136    // padded A column stride, elems
#define SO_LD   68     // padded sOut row stride, elems

// Precomputed weight data (prep kernel, every launch — deterministic)
__device__ __nv_bfloat16 g_wbf[K_ * O_];
__device__ float         g_w2[O_];

__global__ void gauss_prep_kernel(const float* __restrict__ w) {
    int t = threadIdx.x;
    for (int i = t; i < K_ * O_; i += NTHREADS)
        g_wbf[i] = __float2bfloat16(w[i]);
    if (t < O_) {
        float s = 0.f;
        #pragma unroll 4
        for (int k = 0; k < K_; ++k) {
            float v = w[k * O_ + t];
            s += v * v;
        }
        g_w2[t] = s;
    }
}

__device__ __forceinline__ void cp_async16(void* smem_dst, const void* gmem_src) {
    unsigned s = (unsigned)__cvta_generic_to_shared(smem_dst);
    asm volatile("cp.async.cg.shared.global [%0], [%1], 16;\n" :: "r"(s), "l"(gmem_src));
}
__device__ __forceinline__ void cp_commit() {
    asm volatile("cp.async.commit_group;\n");
}
template<int N> __device__ __forceinline__ void cp_wait() {
    asm volatile("cp.async.wait_group %0;\n" :: "n"(N));
}

extern __shared__ char g_smem[];

// Shared layout (bytes):
//   ws   : [0, 41472)                K_*72 bf16 (padded weights [k][o])
//   xsc  : [41472, 58880)            2 x CH*136 bf16 (A chunk, double buffered)
//   xf   : [58880, 108032)           3 x CH*128 f32 (cp.async staging)
//   x2p  : [108032, 109056)          2*128 f32
//   x2   : [109056, 109568)          128 f32
//   w2s  : [109568, 109824)          64 f32
//   bs   : [109824, 110080)          64 f32
//   sOut : aliases xf (128*68*4 = 34816 <= 49152)
#define OFF_WS   0
#define OFF_XSC  41472
#define OFF_XF   58880
#define OFF_X2P  108032
#define OFF_X2   109056
#define OFF_W2S  109568
#define OFF_BS   109824
#define SMEM_BYTES 110080

__global__ __launch_bounds__(NTHREADS, 2)
void gauss_main_kernel(const float* __restrict__ x,
                       const float* __restrict__ bias,
                       const float* __restrict__ gamma_p,
                       float* __restrict__ out) {
    __nv_bfloat16* ws  = (__nv_bfloat16*)(g_smem + OFF_WS);
    __nv_bfloat16* xsc = (__nv_bfloat16*)(g_smem + OFF_XSC);
    float*         xf  = (float*)(g_smem + OFF_XF);
    float*         x2p = (float*)(g_smem + OFF_X2P);
    float*         x2  = (float*)(g_smem + OFF_X2);
    float*         w2s = (float*)(g_smem + OFF_W2S);
    float*         bs  = (float*)(g_smem + OFF_BS);
    float*         sOut = xf;   // alias, used after pipeline drains

    const int t    = threadIdx.x;
    const int warp = t >> 5;
    const int l    = t & 127;
    const int kg   = t >> 7;        // 0..1 (k half within chunk)
    const int bx   = blockIdx.x;
    const int b    = bx >> 7;
    const int l0   = (bx & 127) * LT;

    const float* xb = x + (size_t)b * K_ * L_ + l0;

    // --- stage W (padded) + w2 + bias ---
    for (int i = t; i < K_ * O_; i += NTHREADS) {
        int k = i >> 6, o = i & 63;
        ws[k * WS_LD + o] = g_wbf[i];
    }
    if (t < O_) { w2s[t] = g_w2[t]; bs[t] = bias[t]; }

    // --- cp.async pipeline prologue: issue first STAGES chunks ---
    #pragma unroll
    for (int c = 0; c < STAGES; ++c) {
        float* dstf = xf + (c % STAGES) * (CH * 128);
        #pragma unroll
        for (int i = t; i < CH * 32; i += NTHREADS) {
            int row = i >> 5, seg = i & 31;
            cp_async16(dstf + row * 128 + seg * 4,
                       xb + (size_t)(c * CH + row) * L_ + seg * 4);
        }
        cp_commit();
    }

    wmma::fragment<wmma::accumulator, 16, 16, 16, float> accf[4];
    #pragma unroll
    for (int i = 0; i < 4; ++i) wmma::fill_fragment(accf[i], 0.f);
    float acc = 0.f;

    // --- pipelined mainloop over 9 k-chunks ---
    #pragma unroll 1
    for (int c = 0; c < NCH; ++c) {
        cp_wait<STAGES - 1>();
        __syncthreads();                         // stage (c%3) visible to all

        const float*   src = xf  + (c % STAGES) * (CH * 128);
        __nv_bfloat16* dA  = xsc + (c & 1) * (CH * XA_LD);

        // convert fp32 -> bf16 (padded A layout [k][l]) + x2 accumulation
        #pragma unroll
        for (int kk = 0; kk < 16; ++kk) {
            int k = kg * 16 + kk;
            float v = src[k * 128 + l];
            dA[k * XA_LD + l] = __float2bfloat16(v);
            acc = fmaf(v, v, acc);
        }
        __syncthreads();                         // all reads of stage done + dA visible

        // refill this stage with chunk c+3
        if (c + STAGES < NCH) {
            float* dstf = xf + (c % STAGES) * (CH * 128);
            #pragma unroll
            for (int i = t; i < CH * 32; i += NTHREADS) {
                int row = i >> 5, seg = i & 31;
                cp_async16(dstf + row * 128 + seg * 4,
                           xb + (size_t)((c + STAGES) * CH + row) * L_ + seg * 4);
            }
        }
        cp_commit();

        // MMA: 2 k-steps on this chunk; each warp owns one 16-l row tile
        #pragma unroll
        for (int ks = 0; ks < 2; ++ks) {
            wmma::fragment<wmma::matrix_a, 16, 16, 16, __nv_bfloat16, wmma::col_major> af;
            wmma::load_matrix_sync(af, dA + ks * 16 * XA_LD + warp * 16, XA_LD);
            #pragma unroll
            for (int ot = 0; ot < 4; ++ot) {
                wmma::fragment<wmma::matrix_b, 16, 16, 16, __nv_bfloat16, wmma::row_major> bf;
                wmma::load_matrix_sync(bf, ws + (c * CH + ks * 16) * WS_LD + ot * 16, WS_LD);
                wmma::mma_sync(accf[ot], af, bf, accf[ot]);
            }
        }
    }

    // --- epilogue ---
    x2p[kg * 128 + l] = acc;
    cp_wait<0>();
    __syncthreads();                 // all MMA/x2p done; xf free for sOut

    #pragma unroll
    for (int ot = 0; ot < 4; ++ot)
        wmma::store_matrix_sync(sOut + (warp * 16) * SO_LD + ot * 16, accf[ot],
                                SO_LD, wmma::mem_row_major);
    if (t < 128) x2[t] = x2p[t] + x2p[128 + t];
    __syncthreads();

    const float gamma = *gamma_p;
    float* ob = out + ((size_t)b * L_ + l0) * O_;
    #pragma unroll
    for (int idx = t; idx < LT * O_; idx += NTHREADS) {
        const int li = idx >> 6;
        const int o  = idx & 63;
        const float d2 = x2[li] + w2s[o] - 2.f * sOut[li * SO_LD + o];
        ob[idx] = __expf(-gamma * d2) + bs[o];
    }
}

extern "C" void kernel_launch(void* const* d_in, const int* in_sizes, int n_in,
                              void* d_out, int out_size) {
    const float* x     = (const float*)d_in[0];
    const float* w     = (const float*)d_in[1];
    const float* bias  = (const float*)d_in[2];
    const float* gamma = (const float*)d_in[3];
    float* out = (float*)d_out;

    cudaFuncSetAttribute(gauss_main_kernel,
                         cudaFuncAttributeMaxDynamicSharedMemorySize, SMEM_BYTES);

    gauss_prep_kernel<<<1, NTHREADS>>>(w);
    gauss_main_kernel<<<B_ * (L_ / LT), NTHREADS, SMEM_BYTES>>>(x, bias, gamma, out);
    (void)in_sizes; (void)n_in; (void)out_size;
}

// round 4
// speedup vs baseline: 2.5731x; 1.0253x over previous
#include <cuda_runtime.h>
#include <cuda_bf16.h>
#include <cstdint>

// ---------------- problem constants ----------------
#define B_   8
#define K_   288
#define L_   16384
#define O_   64
#define NT   256
#define CH   32          // k per chunk
#define NCH  9           // 288/32
#define NKS  18          // K/16 k-steps

// staging geometry (per warp, per stage): [k=32][l=16 fp32, padded to 20]
#define LSTR 20
#define WARP_STG_F   (CH * LSTR)          // 640 floats
#define STAGE_F      (8 * WARP_STG_F)     // 5120 floats
#define SMEM_BYTES   (3 * STAGE_F * 4)    // 61440 bytes

// ---------------- prep outputs ----------------
// B fragments for mma.m16n8k16 (bf16, col-major B): [ks][nt][lane] -> {b0,b1}
__device__ uint2  g_wfrag[NKS * 8 * 32];
// packed epilogue constants: g_wb4[j] = (w2[2j], bias[2j], w2[2j+1], bias[2j+1])
__device__ float4 g_wb4[O_ / 2];

__global__ void gauss_prep_kernel(const float* __restrict__ w,
                                  const float* __restrict__ bias) {
    int t = threadIdx.x;
    if (blockIdx.x < NKS) {
        // one block per k-step: 8 n-tiles x 32 lanes
        int ks   = blockIdx.x;
        int nt   = t >> 5;
        int lane = t & 31;
        int k = ks * 16 + (lane & 3) * 2;
        int o = nt * 8 + (lane >> 2);
        // wv[k][o] = w_flat[k*64 + o]
        __nv_bfloat162 b0 = __floats2bfloat162_rn(w[k * O_ + o], w[(k + 1) * O_ + o]);
        __nv_bfloat162 b1 = __floats2bfloat162_rn(w[(k + 8) * O_ + o], w[(k + 9) * O_ + o]);
        uint2 v;
        v.x = *reinterpret_cast<uint32_t*>(&b0);
        v.y = *reinterpret_cast<uint32_t*>(&b1);
        g_wfrag[(ks * 8 + nt) * 32 + lane] = v;
    } else {
        __shared__ float s_w2[O_];
        if (t < O_) {
            float s = 0.f;
            #pragma unroll 4
            for (int k = 0; k < K_; ++k) { float v = w[k * O_ + t]; s += v * v; }
            s_w2[t] = s;
        }
        __syncthreads();
        if (t < O_ / 2) {
            float4 r;
            r.x = s_w2[2 * t];     r.y = bias[2 * t];
            r.z = s_w2[2 * t + 1]; r.w = bias[2 * t + 1];
            g_wb4[t] = r;
        }
    }
}

// ---------------- PTX helpers ----------------
__device__ __forceinline__ void cp_async16(void* smem_dst, const void* gmem_src) {
    unsigned s = (unsigned)__cvta_generic_to_shared(smem_dst);
    asm volatile("cp.async.cg.shared.global [%0], [%1], 16;\n"
                 :: "r"(s), "l"(gmem_src) : "memory");
}
__device__ __forceinline__ void cp_commit() {
    asm volatile("cp.async.commit_group;\n" ::: "memory");
}
template<int N> __device__ __forceinline__ void cp_wait() {
    asm volatile("cp.async.wait_group %0;\n" :: "n"(N) : "memory");
}
__device__ __forceinline__ uint32_t packbf(float lo, float hi) {
    __nv_bfloat162 h = __floats2bfloat162_rn(lo, hi);
    return *reinterpret_cast<uint32_t*>(&h);
}
__device__ __forceinline__ void mma16816(float* c,
                                         uint32_t a0, uint32_t a1, uint32_t a2, uint32_t a3,
                                         uint32_t b0, uint32_t b1) {
    asm volatile(
        "mma.sync.aligned.m16n8k16.row.col.f32.bf16.bf16.f32 "
        "{%0,%1,%2,%3}, {%4,%5,%6,%7}, {%8,%9}, {%0,%1,%2,%3};"
        : "+f"(c[0]), "+f"(c[1]), "+f"(c[2]), "+f"(c[3])
        : "r"(a0), "r"(a1), "r"(a2), "r"(a3), "r"(b0), "r"(b1));
}

extern __shared__ float g_stg[];   // 3 stages x 8 warps x [32][20] fp32

// issue warp-private cp.async for chunk c (x slice: 32 k-rows x 16 l-floats)
__device__ __forceinline__ void issue_chunk(const float* __restrict__ xb,
                                            int c, int warp, int lane) {
    float* dst = g_stg + (c % 3) * STAGE_F + warp * WARP_STG_F;
    #pragma unroll
    for (int q = 0; q < 4; ++q) {
        int idx = lane + q * 32;          // 0..127
        int kr  = idx >> 2;               // 0..31
        int sg  = idx & 3;                // 0..3 (16B segment)
        cp_async16(dst + kr * LSTR + sg * 4,
                   xb + (size_t)(c * CH + kr) * L_ + sg * 4);
    }
}

__global__ __launch_bounds__(NT, 3)
void gauss_main_kernel(const float* __restrict__ x,
                       const float* __restrict__ gamma_p,
                       float* __restrict__ out) {
    const int t    = threadIdx.x;
    const int warp = t >> 5;
    const int lane = t & 31;
    const int bx   = blockIdx.x;
    const int b    = bx >> 7;
    const int l0   = (bx & 127) * 128;

    // warp's global x base: its 16-l slice
    const float* xb = x + (size_t)b * K_ * L_ + l0 + warp * 16;

    const int kc  = (lane & 3) * 2;   // fragment k base within 16-k step
    const int llo = lane >> 2;        // fragment row (l) within 16-l tile

    float acc[8][4];
    #pragma unroll
    for (int i = 0; i < 8; ++i)
        #pragma unroll
        for (int j = 0; j < 4; ++j) acc[i][j] = 0.f;
    float x2lo = 0.f, x2hi = 0.f;

    // pipeline prologue: chunks 0..2
    #pragma unroll
    for (int p = 0; p < 3; ++p) { issue_chunk(xb, p, warp, lane); cp_commit(); }

    // ---------------- warp-autonomous mainloop ----------------
    #pragma unroll 1
    for (int c = 0; c < NCH; ++c) {
        cp_wait<2>();
        __syncwarp();                     // all lanes' copies of chunk c done+visible

        const float* sb = g_stg + (c % 3) * STAGE_F + warp * WARP_STG_F;
        #pragma unroll
        for (int h = 0; h < 2; ++h) {
            const float* p0 = sb + h * 16 * LSTR;
            // A-fragment elements (fp32), conflict-free LDS
            float vl0 = p0[(kc + 0) * LSTR + llo];
            float vl1 = p0[(kc + 1) * LSTR + llo];
            float vl8 = p0[(kc + 8) * LSTR + llo];
            float vl9 = p0[(kc + 9) * LSTR + llo];
            float vh0 = p0[(kc + 0) * LSTR + llo + 8];
            float vh1 = p0[(kc + 1) * LSTR + llo + 8];
            float vh8 = p0[(kc + 8) * LSTR + llo + 8];
            float vh9 = p0[(kc + 9) * LSTR + llo + 8];

            // fused x2 accumulation (each element read exactly once per lane)
            x2lo = fmaf(vl0, vl0, x2lo); x2lo = fmaf(vl1, vl1, x2lo);
            x2lo = fmaf(vl8, vl8, x2lo); x2lo = fmaf(vl9, vl9, x2lo);
            x2hi = fmaf(vh0, vh0, x2hi); x2hi = fmaf(vh1, vh1, x2hi);
            x2hi = fmaf(vh8, vh8, x2hi); x2hi = fmaf(vh9, vh9, x2hi);

            // pack A fragment (row-major m16k16 bf16)
            uint32_t A0 = packbf(vl0, vl1);   // row llo,   k-lo
            uint32_t A1 = packbf(vh0, vh1);   // row llo+8, k-lo
            uint32_t A2 = packbf(vl8, vl9);   // row llo,   k-hi
            uint32_t A3 = packbf(vh8, vh9);   // row llo+8, k-hi

            const int ks = c * 2 + h;
            const uint2* wf = g_wfrag + (ks * 8) * 32 + lane;
            #pragma unroll
            for (int nt = 0; nt < 8; ++nt) {
                uint2 bb = wf[nt * 32];       // coalesced LDG.64, L1-resident
                mma16816(acc[nt], A0, A1, A2, A3, bb.x, bb.y);
            }
        }

        __syncwarp();                     // all lanes done reading stage (c%3)
        if (c + 3 < NCH) issue_chunk(xb, c + 3, warp, lane);
        cp_commit();                      // uniform group accounting (empty ok)
    }

    // x2 reduction across the 4 lanes sharing each l row
    x2lo += __shfl_xor_sync(0xFFFFFFFF, x2lo, 1);
    x2lo += __shfl_xor_sync(0xFFFFFFFF, x2lo, 2);
    x2hi += __shfl_xor_sync(0xFFFFFFFF, x2hi, 1);
    x2hi += __shfl_xor_sync(0xFFFFFFFF, x2hi, 2);

    // ---------------- register epilogue ----------------
    const float gamma = __ldg(gamma_p);
    float* ob = out + ((size_t)b * L_ + l0 + warp * 16) * O_;

    #pragma unroll
    for (int nt = 0; nt < 8; ++nt) {
        const int o = nt * 8 + kc;
        float4 wb = g_wb4[nt * 4 + (lane & 3)];   // (w2[o],bias[o],w2[o+1],bias[o+1])
        float2 r0, r1;
        r0.x = __expf(-gamma * (x2lo + wb.x - 2.f * acc[nt][0])) + wb.y;
        r0.y = __expf(-gamma * (x2lo + wb.z - 2.f * acc[nt][1])) + wb.w;
        r1.x = __expf(-gamma * (x2hi + wb.x - 2.f * acc[nt][2])) + wb.y;
        r1.y = __expf(-gamma * (x2hi + wb.z - 2.f * acc[nt][3])) + wb.w;
        *reinterpret_cast<float2*>(ob + (size_t)llo * O_ + o)       = r0;
        *reinterpret_cast<float2*>(ob + (size_t)(llo + 8) * O_ + o) = r1;
    }
}

extern "C" void kernel_launch(void* const* d_in, const int* in_sizes, int n_in,
                              void* d_out, int out_size) {
    const float* x     = (const float*)d_in[0];
    const float* w     = (const float*)d_in[1];
    const float* bias  = (const float*)d_in[2];
    const float* gamma = (const float*)d_in[3];
    float* out = (float*)d_out;

    cudaFuncSetAttribute(gauss_main_kernel,
                         cudaFuncAttributeMaxDynamicSharedMemorySize, SMEM_BYTES);

    gauss_prep_kernel<<<NKS + 1, NT>>>(w, bias);
    gauss_main_kernel<<<B_ * (L_ / 128), NT, SMEM_BYTES>>>(x, gamma, out);
    (void)in_sizes; (void)n_in; (void)out_size;
}

// round 5
// speedup vs baseline: 2.8151x; 1.0941x over previous
#include <cuda_runtime.h>
#include <cuda_bf16.h>
#include <cstdint>

// ---------------- problem constants ----------------
#define B_   8
#define K_   288
#define L_   16384
#define O_   64
#define NT   256
#define CH   16          // k per chunk = one k-step
#define NCH  18          // 288/16
#define NKS  18
#define NSTG 6           // pipeline stages

// staging geometry (per warp, per stage): [k=16][l=16 fp32, padded to 20]
#define LSTR 20
#define WARP_STG_F   (CH * LSTR)               // 320 floats
#define STAGE_F      (8 * WARP_STG_F)          // 2560 floats
#define SMEM_BYTES   (NSTG * STAGE_F * 4)      // 61440 bytes

// ---------------- prep outputs ----------------
// B fragments for mma.m16n8k16 (bf16, col-major B): [ks][nt][lane] -> {b0,b1}
__device__ uint2  g_wfrag[NKS * 8 * 32];
// packed epilogue constants: g_wb4[j] = (w2[2j], bias[2j], w2[2j+1], bias[2j+1])
__device__ float4 g_wb4[O_ / 2];

__global__ void gauss_prep_kernel(const float* __restrict__ w,
                                  const float* __restrict__ bias) {
    int t = threadIdx.x;
    if (blockIdx.x < NKS) {
        int ks   = blockIdx.x;
        int nt   = t >> 5;
        int lane = t & 31;
        int k = ks * 16 + (lane & 3) * 2;
        int o = nt * 8 + (lane >> 2);
        __nv_bfloat162 b0 = __floats2bfloat162_rn(w[k * O_ + o], w[(k + 1) * O_ + o]);
        __nv_bfloat162 b1 = __floats2bfloat162_rn(w[(k + 8) * O_ + o], w[(k + 9) * O_ + o]);
        uint2 v;
        v.x = *reinterpret_cast<uint32_t*>(&b0);
        v.y = *reinterpret_cast<uint32_t*>(&b1);
        g_wfrag[(ks * 8 + nt) * 32 + lane] = v;
    } else {
        // parallel w2: 4 threads per o, each 72 k's, combine via shfl
        __shared__ float s_w2[O_];
        int o   = t >> 2;          // 0..63
        int sub = t & 3;
        float s = 0.f;
        #pragma unroll 8
        for (int k = sub; k < K_; k += 4) { float v = w[k * O_ + o]; s = fmaf(v, v, s); }
        s += __shfl_xor_sync(0xFFFFFFFF, s, 1);
        s += __shfl_xor_sync(0xFFFFFFFF, s, 2);
        if (sub == 0) s_w2[o] = s;
        __syncthreads();
        if (t < O_ / 2) {
            float4 r;
            r.x = s_w2[2 * t];     r.y = bias[2 * t];
            r.z = s_w2[2 * t + 1]; r.w = bias[2 * t + 1];
            g_wb4[t] = r;
        }
    }
}

// ---------------- PTX helpers ----------------
__device__ __forceinline__ void cp_async16(void* smem_dst, const void* gmem_src) {
    unsigned s = (unsigned)__cvta_generic_to_shared(smem_dst);
    asm volatile("cp.async.cg.shared.global [%0], [%1], 16;\n"
                 :: "r"(s), "l"(gmem_src) : "memory");
}
__device__ __forceinline__ void cp_commit() {
    asm volatile("cp.async.commit_group;\n" ::: "memory");
}
template<int N> __device__ __forceinline__ void cp_wait() {
    asm volatile("cp.async.wait_group %0;\n" :: "n"(N) : "memory");
}
__device__ __forceinline__ uint32_t packbf(float lo, float hi) {
    __nv_bfloat162 h = __floats2bfloat162_rn(lo, hi);
    return *reinterpret_cast<uint32_t*>(&h);
}
__device__ __forceinline__ void mma16816(float* c,
                                         uint32_t a0, uint32_t a1, uint32_t a2, uint32_t a3,
                                         uint32_t b0, uint32_t b1) {
    asm volatile(
        "mma.sync.aligned.m16n8k16.row.col.f32.bf16.bf16.f32 "
        "{%0,%1,%2,%3}, {%4,%5,%6,%7}, {%8,%9}, {%0,%1,%2,%3};"
        : "+f"(c[0]), "+f"(c[1]), "+f"(c[2]), "+f"(c[3])
        : "r"(a0), "r"(a1), "r"(a2), "r"(a3), "r"(b0), "r"(b1));
}

extern __shared__ float g_stg[];   // NSTG stages x 8 warps x [16][20] fp32

// warp-private cp.async for chunk c (16 k-rows x 16 l-floats = 1 KB)
__device__ __forceinline__ void issue_chunk(const float* __restrict__ xb,
                                            int c, int warp, int lane) {
    float* dst = g_stg + (c % NSTG) * STAGE_F + warp * WARP_STG_F;
    #pragma unroll
    for (int q = 0; q < 2; ++q) {
        int idx = lane + q * 32;          // 0..63
        int kr  = idx >> 2;               // 0..15
        int sg  = idx & 3;                // 16B segment
        cp_async16(dst + kr * LSTR + sg * 4,
                   xb + (size_t)(c * CH + kr) * L_ + sg * 4);
    }
}

__global__ __launch_bounds__(NT, 3)
void gauss_main_kernel(const float* __restrict__ x,
                       const float* __restrict__ gamma_p,
                       float* __restrict__ out) {
    const int t    = threadIdx.x;
    const int warp = t >> 5;
    const int lane = t & 31;
    const int bx   = blockIdx.x;
    const int b    = bx >> 7;
    const int l0   = (bx & 127) * 128;

    const float* xb = x + (size_t)b * K_ * L_ + l0 + warp * 16;

    const int kc  = (lane & 3) * 2;   // fragment k base within k-step
    const int llo = lane >> 2;        // fragment row (l) within 16-l tile

    float acc[8][4];
    #pragma unroll
    for (int i = 0; i < 8; ++i)
        #pragma unroll
        for (int j = 0; j < 4; ++j) acc[i][j] = 0.f;
    float x2lo = 0.f, x2hi = 0.f;

    // prologue: 5 chunks in flight
    #pragma unroll
    for (int p = 0; p < NSTG - 1; ++p) { issue_chunk(xb, p, warp, lane); cp_commit(); }

    // ---------------- warp-autonomous mainloop ----------------
    #pragma unroll 1
    for (int c = 0; c < NCH; ++c) {
        cp_wait<NSTG - 2>();              // chunk c landed
        __syncwarp();

        // refill FIRST: stage (c+5)%6 held chunk c-1, already consumed
        if (c + NSTG - 1 < NCH) issue_chunk(xb, c + NSTG - 1, warp, lane);
        cp_commit();

        const float* p0 = g_stg + (c % NSTG) * STAGE_F + warp * WARP_STG_F;
        float vl0 = p0[(kc + 0) * LSTR + llo];
        float vl1 = p0[(kc + 1) * LSTR + llo];
        float vl8 = p0[(kc + 8) * LSTR + llo];
        float vl9 = p0[(kc + 9) * LSTR + llo];
        float vh0 = p0[(kc + 0) * LSTR + llo + 8];
        float vh1 = p0[(kc + 1) * LSTR + llo + 8];
        float vh8 = p0[(kc + 8) * LSTR + llo + 8];
        float vh9 = p0[(kc + 9) * LSTR + llo + 8];

        x2lo = fmaf(vl0, vl0, x2lo); x2lo = fmaf(vl1, vl1, x2lo);
        x2lo = fmaf(vl8, vl8, x2lo); x2lo = fmaf(vl9, vl9, x2lo);
        x2hi = fmaf(vh0, vh0, x2hi); x2hi = fmaf(vh1, vh1, x2hi);
        x2hi = fmaf(vh8, vh8, x2hi); x2hi = fmaf(vh9, vh9, x2hi);

        uint32_t A0 = packbf(vl0, vl1);
        uint32_t A1 = packbf(vh0, vh1);
        uint32_t A2 = packbf(vl8, vl9);
        uint32_t A3 = packbf(vh8, vh9);

        const uint2* wf = g_wfrag + (c * 8) * 32 + lane;
        #pragma unroll
        for (int nt = 0; nt < 8; ++nt) {
            uint2 bb = wf[nt * 32];       // L1-resident
            mma16816(acc[nt], A0, A1, A2, A3, bb.x, bb.y);
        }
        __syncwarp();                     // stage (c%6) free for reuse at c+6... (c+5 issue next iter)
    }

    // x2 reduction across the 4 lanes sharing each l row
    x2lo += __shfl_xor_sync(0xFFFFFFFF, x2lo, 1);
    x2lo += __shfl_xor_sync(0xFFFFFFFF, x2lo, 2);
    x2hi += __shfl_xor_sync(0xFFFFFFFF, x2hi, 1);
    x2hi += __shfl_xor_sync(0xFFFFFFFF, x2hi, 2);

    // ---------------- register epilogue ----------------
    const float gamma = __ldg(gamma_p);
    float* ob = out + ((size_t)b * L_ + l0 + warp * 16) * O_;

    #pragma unroll
    for (int nt = 0; nt < 8; ++nt) {
        const int o = nt * 8 + kc;
        float4 wb = g_wb4[nt * 4 + (lane & 3)];
        float2 r0, r1;
        r0.x = __expf(-gamma * (x2lo + wb.x - 2.f * acc[nt][0])) + wb.y;
        r0.y = __expf(-gamma * (x2lo + wb.z - 2.f * acc[nt][1])) + wb.w;
        r1.x = __expf(-gamma * (x2hi + wb.x - 2.f * acc[nt][2])) + wb.y;
        r1.y = __expf(-gamma * (x2hi + wb.z - 2.f * acc[nt][3])) + wb.w;
        *reinterpret_cast<float2*>(ob + (size_t)llo * O_ + o)       = r0;
        *reinterpret_cast<float2*>(ob + (size_t)(llo + 8) * O_ + o) = r1;
    }
}

extern "C" void kernel_launch(void* const* d_in, const int* in_sizes, int n_in,
                              void* d_out, int out_size) {
    const float* x     = (const float*)d_in[0];
    const float* w     = (const float*)d_in[1];
    const float* bias  = (const float*)d_in[2];
    const float* gamma = (const float*)d_in[3];
    float* out = (float*)d_out;

    cudaFuncSetAttribute(gauss_main_kernel,
                         cudaFuncAttributeMaxDynamicSharedMemorySize, SMEM_BYTES);

    gauss_prep_kernel<<<NKS + 1, NT>>>(w, bias);
    gauss_main_kernel<<<B_ * (L_ / 128), NT, SMEM_BYTES>>>(x, gamma, out);
    (void)in_sizes; (void)n_in; (void)out_size;
}

// round 6
// speedup vs baseline: 4.5131x; 1.6031x over previous
#include <cuda_runtime.h>
#include <cuda_bf16.h>
#include <cstdint>

// ---------------- problem constants ----------------
#define B_   8
#define K_   288
#define L_   16384
#define O_   64
#define NT   256
#define LT   256         // l-tile per CTA
#define CH   16          // k per chunk = one k-step
#define NCH  18
#define NKS  18
#define NSTG 4

// staging: [k=16][l=256 fp32 padded to 260] per stage
#define LSTR 260
#define STAGE_F (CH * LSTR)                 // 4160 floats
#define SMEM_BYTES (NSTG * STAGE_F * 4)     // 66560 bytes

// ---------------- prep outputs ----------------
__device__ uint2  g_wfrag[NKS * 8 * 32];    // B fragments [ks][nt][lane]
__device__ float4 g_wb4[O_ / 2];            // (w2,bias) pairs

__global__ void gauss_prep_kernel(const float* __restrict__ w,
                                  const float* __restrict__ bias) {
    int t = threadIdx.x;
    if (blockIdx.x < NKS) {
        int ks   = blockIdx.x;
        int nt   = t >> 5;
        int lane = t & 31;
        int k = ks * 16 + (lane & 3) * 2;
        int o = nt * 8 + (lane >> 2);
        __nv_bfloat162 b0 = __floats2bfloat162_rn(w[k * O_ + o], w[(k + 1) * O_ + o]);
        __nv_bfloat162 b1 = __floats2bfloat162_rn(w[(k + 8) * O_ + o], w[(k + 9) * O_ + o]);
        uint2 v;
        v.x = *reinterpret_cast<uint32_t*>(&b0);
        v.y = *reinterpret_cast<uint32_t*>(&b1);
        g_wfrag[(ks * 8 + nt) * 32 + lane] = v;
    } else {
        __shared__ float s_w2[O_];
        int o   = t >> 2;
        int sub = t & 3;
        float s = 0.f;
        #pragma unroll 8
        for (int k = sub; k < K_; k += 4) { float v = w[k * O_ + o]; s = fmaf(v, v, s); }
        s += __shfl_xor_sync(0xFFFFFFFF, s, 1);
        s += __shfl_xor_sync(0xFFFFFFFF, s, 2);
        if (sub == 0) s_w2[o] = s;
        __syncthreads();
        if (t < O_ / 2) {
            float4 r;
            r.x = s_w2[2 * t];     r.y = bias[2 * t];
            r.z = s_w2[2 * t + 1]; r.w = bias[2 * t + 1];
            g_wb4[t] = r;
        }
    }
}

// ---------------- PTX helpers ----------------
__device__ __forceinline__ void cp_async16(void* smem_dst, const void* gmem_src) {
    unsigned s = (unsigned)__cvta_generic_to_shared(smem_dst);
    asm volatile("cp.async.cg.shared.global [%0], [%1], 16;\n"
                 :: "r"(s), "l"(gmem_src) : "memory");
}
__device__ __forceinline__ void cp_commit() {
    asm volatile("cp.async.commit_group;\n" ::: "memory");
}
template<int N> __device__ __forceinline__ void cp_wait() {
    asm volatile("cp.async.wait_group %0;\n" :: "n"(N) : "memory");
}
__device__ __forceinline__ uint32_t packbf(float lo, float hi) {
    __nv_bfloat162 h = __floats2bfloat162_rn(lo, hi);
    return *reinterpret_cast<uint32_t*>(&h);
}
__device__ __forceinline__ void mma16816(float* c,
                                         uint32_t a0, uint32_t a1, uint32_t a2, uint32_t a3,
                                         uint32_t b0, uint32_t b1) {
    asm volatile(
        "mma.sync.aligned.m16n8k16.row.col.f32.bf16.bf16.f32 "
        "{%0,%1,%2,%3}, {%4,%5,%6,%7}, {%8,%9}, {%0,%1,%2,%3};"
        : "+f"(c[0]), "+f"(c[1]), "+f"(c[2]), "+f"(c[3])
        : "r"(a0), "r"(a1), "r"(a2), "r"(a3), "r"(b0), "r"(b1));
}

extern __shared__ float g_stg[];

// cooperative staging: warp w loads k-rows {2w, 2w+1}, each as 2 x 512B
// contiguous LDGSTS (full 1 KB row back-to-back).
__device__ __forceinline__ void issue_chunk(const float* __restrict__ xb,
                                            int c, int warp, int lane) {
    float* dst = g_stg + (c & (NSTG - 1)) * STAGE_F;
    #pragma unroll
    for (int r = 0; r < 2; ++r) {
        int kr = warp * 2 + r;
        const float* src = xb + (size_t)(c * CH + kr) * L_;
        float* d = dst + kr * LSTR;
        #pragma unroll
        for (int j = 0; j < 2; ++j)
            cp_async16(d + j * 128 + lane * 4, src + j * 128 + lane * 4);
    }
}

__global__ __launch_bounds__(NT, 2)
void gauss_main_kernel(const float* __restrict__ x,
                       const float* __restrict__ gamma_p,
                       float* __restrict__ out) {
    const int t    = threadIdx.x;
    const int warp = t >> 5;
    const int lane = t & 31;
    const int bx   = blockIdx.x;
    const int b    = bx >> 6;              // 64 l-tiles per batch
    const int l0   = (bx & 63) * LT;

    const float* xb = x + (size_t)b * K_ * L_ + l0;

    const int kc  = (lane & 3) * 2;
    const int llo = lane >> 2;
    const int lw  = warp * 32;             // warp's l offset within tile

    float acc[2][8][4];
    #pragma unroll
    for (int s = 0; s < 2; ++s)
        #pragma unroll
        for (int i = 0; i < 8; ++i)
            #pragma unroll
            for (int j = 0; j < 4; ++j) acc[s][i][j] = 0.f;
    float x2a[2][2] = {{0.f, 0.f}, {0.f, 0.f}};

    // prologue: 3 chunks in flight
    #pragma unroll
    for (int p = 0; p < NSTG - 1; ++p) { issue_chunk(xb, p, warp, lane); cp_commit(); }

    // ---------------- mainloop, 1 barrier per chunk ----------------
    #pragma unroll 1
    for (int c = 0; c < NCH; ++c) {
        cp_wait<NSTG - 2>();               // own copies of chunk c done
        __syncthreads();                   // all warps' copies visible; c-1 consumed

        if (c + NSTG - 1 < NCH) issue_chunk(xb, c + NSTG - 1, warp, lane);
        cp_commit();

        const float* st = g_stg + (c & (NSTG - 1)) * STAGE_F;
        const uint2* wf = g_wfrag + (c * 8) * 32 + lane;

        #pragma unroll
        for (int s = 0; s < 2; ++s) {
            const float* p0 = st + lw + s * 16 + llo;
            float vl0 = p0[(kc + 0) * LSTR];
            float vl1 = p0[(kc + 1) * LSTR];
            float vl8 = p0[(kc + 8) * LSTR];
            float vl9 = p0[(kc + 9) * LSTR];
            float vh0 = p0[(kc + 0) * LSTR + 8];
            float vh1 = p0[(kc + 1) * LSTR + 8];
            float vh8 = p0[(kc + 8) * LSTR + 8];
            float vh9 = p0[(kc + 9) * LSTR + 8];

            x2a[s][0] = fmaf(vl0, vl0, x2a[s][0]); x2a[s][0] = fmaf(vl1, vl1, x2a[s][0]);
            x2a[s][0] = fmaf(vl8, vl8, x2a[s][0]); x2a[s][0] = fmaf(vl9, vl9, x2a[s][0]);
            x2a[s][1] = fmaf(vh0, vh0, x2a[s][1]); x2a[s][1] = fmaf(vh1, vh1, x2a[s][1]);
            x2a[s][1] = fmaf(vh8, vh8, x2a[s][1]); x2a[s][1] = fmaf(vh9, vh9, x2a[s][1]);

            uint32_t A0 = packbf(vl0, vl1);
            uint32_t A1 = packbf(vh0, vh1);
            uint32_t A2 = packbf(vl8, vl9);
            uint32_t A3 = packbf(vh8, vh9);

            #pragma unroll
            for (int nt = 0; nt < 8; ++nt) {
                uint2 bb = wf[nt * 32];    // L1-resident
                mma16816(acc[s][nt], A0, A1, A2, A3, bb.x, bb.y);
            }
        }
    }

    // x2 reduction across the 4 lanes sharing each l row
    #pragma unroll
    for (int s = 0; s < 2; ++s)
        #pragma unroll
        for (int hh = 0; hh < 2; ++hh) {
            x2a[s][hh] += __shfl_xor_sync(0xFFFFFFFF, x2a[s][hh], 1);
            x2a[s][hh] += __shfl_xor_sync(0xFFFFFFFF, x2a[s][hh], 2);
        }

    // ---------------- register epilogue ----------------
    const float gamma = __ldg(gamma_p);
    float* ob = out + ((size_t)b * L_ + l0 + lw) * O_;

    #pragma unroll
    for (int s = 0; s < 2; ++s) {
        float* obs = ob + (size_t)(s * 16) * O_;
        #pragma unroll
        for (int nt = 0; nt < 8; ++nt) {
            const int o = nt * 8 + kc;
            float4 wb = g_wb4[nt * 4 + (lane & 3)];
            float2 r0, r1;
            r0.x = __expf(-gamma * (x2a[s][0] + wb.x - 2.f * acc[s][nt][0])) + wb.y;
            r0.y = __expf(-gamma * (x2a[s][0] + wb.z - 2.f * acc[s][nt][1])) + wb.w;
            r1.x = __expf(-gamma * (x2a[s][1] + wb.x - 2.f * acc[s][nt][2])) + wb.y;
            r1.y = __expf(-gamma * (x2a[s][1] + wb.z - 2.f * acc[s][nt][3])) + wb.w;
            *reinterpret_cast<float2*>(obs + (size_t)llo * O_ + o)       = r0;
            *reinterpret_cast<float2*>(obs + (size_t)(llo + 8) * O_ + o) = r1;
        }
    }
}

extern "C" void kernel_launch(void* const* d_in, const int* in_sizes, int n_in,
                              void* d_out, int out_size) {
    const float* x     = (const float*)d_in[0];
    const float* w     = (const float*)d_in[1];
    const float* bias  = (const float*)d_in[2];
    const float* gamma = (const float*)d_in[3];
    float* out = (float*)d_out;

    cudaFuncSetAttribute(gauss_main_kernel,
                         cudaFuncAttributeMaxDynamicSharedMemorySize, SMEM_BYTES);

    gauss_prep_kernel<<<NKS + 1, NT>>>(w, bias);
    gauss_main_kernel<<<B_ * (L_ / LT), NT, SMEM_BYTES>>>(x, gamma, out);
    (void)in_sizes; (void)n_in; (void)out_size;
}